// round 5
// baseline (speedup 1.0000x reference)
#include <cuda_runtime.h>
#include <math_constants.h>

#define B_    64
#define J_    8
#define D_    256
#define NEG_  2048             // K*M
#define NPB_  256              // negatives per block (1 per thread for compaction)
#define SPLIT_ (NEG_/NPB_)     // 8 chunks per batch
#define NBLOCKS_ (B_*SPLIT_)   // 512
#define WPB_  8                // warps per block
#define MAXE_ 3                // register-batched entries per warp (covers n<=24+)
#define INV_TEMP 10.0f
#define EPS_  1e-8f

// Scratch (no allocation allowed -> device globals; zero-initialized)
__device__ float2       g_part[NBLOCKS_];   // per-block (m, s)
__device__ float        g_pos[B_];          // per-batch pos_sim
__device__ unsigned int g_count;            // arrival counter

__device__ __forceinline__ void lse_comb(float& m, float& s, float m2, float s2) {
    float M = fmaxf(m, m2);
    if (M == -CUDART_INF_F) { m = -CUDART_INF_F; s = 0.0f; return; }
    s = s * __expf(m - M) + s2 * __expf(m2 - M);
    m = M;
}

// ---------------------------------------------------------------------------
// 512 blocks x 256 threads. Each block owns 256 negatives of one (batch,chunk):
//   1) all 256 threads test one label each -> compact matching indices to smem
//   2) each warp register-batches up to MAXE_ entries: ALL loads issued first
//      (max MLP), dots computed with ILP, butterfly reductions interleaved
//   3) block publishes one (m,s) partial; last block to arrive finalizes
// ---------------------------------------------------------------------------
__global__ void __launch_bounds__(256, 4) ntxent_kernel(
    const float* __restrict__ childrens,   // (B, J, D)
    const float* __restrict__ pos,         // (B, J, D)
    const float* __restrict__ negs,        // (B, NEG, D)
    const int*   __restrict__ labels,      // (B, J)
    const int*   __restrict__ neg_labels,  // (B, NEG)
    float*       __restrict__ out)
{
    const int bx    = blockIdx.x;
    const int b     = bx >> 3;              // / SPLIT_
    const int chunk = bx & (SPLIT_ - 1);
    const int tid   = threadIdx.x;
    const int warp  = tid >> 5;
    const int lane  = tid & 31;

    __shared__ short s_list[NPB_];
    __shared__ int   s_n;
    __shared__ float s_m[WPB_], s_s[WPB_];
    __shared__ int   s_last;

    const int nbase = chunk * NPB_;

    // ---- issue independent loads early ----
    const int label = __ldg(labels + b * J_ + (J_ - 1));
    const int mylab = __ldg(neg_labels + (size_t)b * NEG_ + nbase + tid);

    const float* cp = childrens + ((size_t)b * J_ + (J_ - 1)) * D_;
    const float4 ca = ((const float4*)cp)[lane];        // child[4*lane .. +3]
    const float4 cb = ((const float4*)cp)[lane + 32];   // child[128+4*lane ..]

    if (tid == 0) s_n = 0;
    __syncthreads();

    // ---- compaction: indices of matching negatives ----
    if (mylab == label) {
        int p = atomicAdd(&s_n, 1);
        s_list[p] = (short)tid;
    }

    // ---- child norm (overlaps compaction) ----
    float cs = ca.x*ca.x + ca.y*ca.y + ca.z*ca.z + ca.w*ca.w
             + cb.x*cb.x + cb.y*cb.y + cb.z*cb.z + cb.w*cb.w;
    #pragma unroll
    for (int o = 16; o; o >>= 1) cs += __shfl_xor_sync(0xffffffffu, cs, o);
    const float invcn = 1.0f / fmaxf(sqrtf(cs), EPS_);

    // ---- chunk-0 blocks, warp 0: pos_sim for this batch ----
    if (chunk == 0 && warp == 0) {
        const float* pp = pos + ((size_t)b * J_ + (J_ - 1)) * D_;
        float4 pa = ((const float4*)pp)[lane];
        float4 pb = ((const float4*)pp)[lane + 32];
        float dot = ca.x*pa.x + ca.y*pa.y + ca.z*pa.z + ca.w*pa.w
                  + cb.x*pb.x + cb.y*pb.y + cb.z*pb.z + cb.w*pb.w;
        float ps  = pa.x*pa.x + pa.y*pa.y + pa.z*pa.z + pa.w*pa.w
                  + pb.x*pb.x + pb.y*pb.y + pb.z*pb.z + pb.w*pb.w;
        #pragma unroll
        for (int o = 16; o; o >>= 1) {
            dot += __shfl_xor_sync(0xffffffffu, dot, o);
            ps  += __shfl_xor_sync(0xffffffffu, ps,  o);
        }
        if (lane == 0)
            g_pos[b] = dot * invcn / fmaxf(sqrtf(ps), EPS_) * INV_TEMP;
    }

    __syncthreads();
    const int n = s_n;

    const float* negbase = negs + ((size_t)b * NEG_ + nbase) * D_;

    float m = -CUDART_INF_F, s = 0.0f;

    // ---- register-batched path: issue ALL owned loads first (max MLP) ----
    float4 Aa[MAXE_], Ac[MAXE_];
    #pragma unroll
    for (int k = 0; k < MAXE_; k++) {
        const int e = warp + k * WPB_;
        if (e < n) {
            const float4* p = (const float4*)(negbase + (size_t)s_list[e] * D_);
            Aa[k] = p[lane];
            Ac[k] = p[lane + 32];
        }
    }

    float dot[MAXE_], ssq[MAXE_];
    #pragma unroll
    for (int k = 0; k < MAXE_; k++) {
        const int e = warp + k * WPB_;
        if (e < n) {
            dot[k] = Aa[k].x*ca.x + Aa[k].y*ca.y + Aa[k].z*ca.z + Aa[k].w*ca.w
                   + Ac[k].x*cb.x + Ac[k].y*cb.y + Ac[k].z*cb.z + Ac[k].w*cb.w;
            ssq[k] = Aa[k].x*Aa[k].x + Aa[k].y*Aa[k].y + Aa[k].z*Aa[k].z + Aa[k].w*Aa[k].w
                   + Ac[k].x*Ac[k].x + Ac[k].y*Ac[k].y + Ac[k].z*Ac[k].z + Ac[k].w*Ac[k].w;
        } else {
            dot[k] = 0.0f; ssq[k] = 1.0f;
        }
    }

    // Interleaved butterfly reductions: 2*MAXE_ independent SHFL chains.
    #pragma unroll
    for (int o = 16; o; o >>= 1) {
        #pragma unroll
        for (int k = 0; k < MAXE_; k++) {
            dot[k] += __shfl_xor_sync(0xffffffffu, dot[k], o);
            ssq[k] += __shfl_xor_sync(0xffffffffu, ssq[k], o);
        }
    }

    // Epilogue: max then sum-exp over the owned batch.
    float sim[MAXE_];
    #pragma unroll
    for (int k = 0; k < MAXE_; k++) {
        const int e = warp + k * WPB_;
        sim[k] = (e < n) ? dot[k] * invcn / fmaxf(sqrtf(ssq[k]), EPS_) * INV_TEMP
                         : -CUDART_INF_F;
        m = fmaxf(m, sim[k]);
    }
    if (m != -CUDART_INF_F) {
        #pragma unroll
        for (int k = 0; k < MAXE_; k++)
            s += (sim[k] != -CUDART_INF_F) ? __expf(sim[k] - m) : 0.0f;
    }

    // ---- rare tail (n > 24): pipelined single-entry path ----
    for (int e = warp + MAXE_ * WPB_; e < n; e += WPB_) {
        const float4* p = (const float4*)(negbase + (size_t)s_list[e] * D_);
        float4 a = p[lane];
        float4 c = p[lane + 32];
        float d2 = a.x*ca.x + a.y*ca.y + a.z*ca.z + a.w*ca.w
                 + c.x*cb.x + c.y*cb.y + c.z*cb.z + c.w*cb.w;
        float q2 = a.x*a.x + a.y*a.y + a.z*a.z + a.w*a.w
                 + c.x*c.x + c.y*c.y + c.z*c.z + c.w*c.w;
        #pragma unroll
        for (int o = 16; o; o >>= 1) {
            d2 += __shfl_xor_sync(0xffffffffu, d2, o);
            q2 += __shfl_xor_sync(0xffffffffu, q2, o);
        }
        float sm = d2 * invcn / fmaxf(sqrtf(q2), EPS_) * INV_TEMP;
        float M2 = fmaxf(m, sm);
        s = s * __expf(m - M2) + __expf(sm - M2);
        m = M2;
    }

    if (lane == 0) { s_m[warp] = m; s_s[warp] = s; }
    __syncthreads();

    // ---- thread 0: combine warp partials, publish block partial ----
    if (tid == 0) {
        float mm = s_m[0], sv = s_s[0];
        #pragma unroll
        for (int w = 1; w < WPB_; w++) lse_comb(mm, sv, s_m[w], s_s[w]);
        g_part[bx] = make_float2(mm, sv);
    }

    // ---- arrival: last block finalizes ----
    __threadfence();
    if (tid == 0) {
        unsigned int old = atomicAdd(&g_count, 1u);
        s_last = (old == NBLOCKS_ - 1) ? 1 : 0;
    }
    __syncthreads();
    if (!s_last) return;

    __threadfence();  // make all blocks' partials visible

    __shared__ float s_loss[B_];
    if (tid < B_) {
        const int batch = tid;
        float m2 = -CUDART_INF_F, s2 = 0.0f;
        #pragma unroll
        for (int k = 0; k < SPLIT_; k++) {
            float2 pr = g_part[batch * SPLIT_ + k];
            lse_comb(m2, s2, pr.x, pr.y);
        }
        const float psim = g_pos[batch];
        lse_comb(m2, s2, psim, 1.0f);
        s_loss[batch] = m2 + logf(s2) - psim;
    }
    __syncthreads();

    if (tid < 32) {
        float v = s_loss[tid] + s_loss[tid + 32];
        #pragma unroll
        for (int o = 16; o; o >>= 1) v += __shfl_xor_sync(0xffffffffu, v, o);
        if (tid == 0) {
            out[0] = v / (2.0f * (float)B_);
            g_count = 0;   // reset for next (graph-replayed) launch
        }
    }
}

extern "C" void kernel_launch(void* const* d_in, const int* in_sizes, int n_in,
                              void* d_out, int out_size) {
    const float* childrens  = (const float*)d_in[0]; // (B, J, D)
    const float* child_pos  = (const float*)d_in[1]; // (B, J, D)
    const float* child_negs = (const float*)d_in[2]; // (B, K, M, D)
    const int*   gt_labels  = (const int*)d_in[3];   // (B, J)
    const int*   gt_negs    = (const int*)d_in[4];   // (B, K, M)
    float* out = (float*)d_out;

    ntxent_kernel<<<NBLOCKS_, 256>>>(childrens, child_pos, child_negs,
                                     gt_labels, gt_negs, out);
}

// round 6
// speedup vs baseline: 1.0030x; 1.0030x over previous
#include <cuda_runtime.h>
#include <math_constants.h>

#define B_    64
#define J_    8
#define D_    256
#define NEG_  2048             // K*M
#define NPB_  256              // negatives per block
#define SPLIT_ (NEG_/NPB_)     // 8 chunks per batch
#define NBLOCKS_ (B_*SPLIT_)   // 512
#define THREADS_ 128
#define WPB_  4                // warps per block
#define MAXE_ 6                // register-batched entries per warp (covers n<=24)
#define INV_TEMP 10.0f
#define EPS_  1e-8f

// Scratch (no allocation allowed -> device globals; zero-initialized)
__device__ float2       g_part[NBLOCKS_];   // per-block (m, s)
__device__ float        g_pos[B_];          // per-batch pos_sim
__device__ unsigned int g_count;            // arrival counter

__device__ __forceinline__ void lse_comb(float& m, float& s, float m2, float s2) {
    float M = fmaxf(m, m2);
    if (M == -CUDART_INF_F) { m = -CUDART_INF_F; s = 0.0f; return; }
    s = s * __expf(m - M) + s2 * __expf(m2 - M);
    m = M;
}

// ---------------------------------------------------------------------------
// 512 blocks x 128 threads (4 warps). Each block owns 256 negatives:
//   1) each thread tests 2 labels (one int2) -> compact match indices to smem
//   2) each warp owns ~4 entries (up to MAXE_=6 batched): ALL loads issued
//      back-to-back (max bytes-in-flight), then ILP'd dots + interleaved
//      butterfly reductions
//   3) block publishes one (m,s) partial; last block to arrive finalizes
// ---------------------------------------------------------------------------
__global__ void __launch_bounds__(THREADS_) ntxent_kernel(
    const float* __restrict__ childrens,   // (B, J, D)
    const float* __restrict__ pos,         // (B, J, D)
    const float* __restrict__ negs,        // (B, NEG, D)
    const int*   __restrict__ labels,      // (B, J)
    const int*   __restrict__ neg_labels,  // (B, NEG)
    float*       __restrict__ out)
{
    const int bx    = blockIdx.x;
    const int b     = bx >> 3;              // / SPLIT_
    const int chunk = bx & (SPLIT_ - 1);
    const int tid   = threadIdx.x;
    const int warp  = tid >> 5;
    const int lane  = tid & 31;

    __shared__ short s_list[NPB_];
    __shared__ int   s_n;
    __shared__ float s_m[WPB_], s_s[WPB_];
    __shared__ int   s_last;

    const int nbase = chunk * NPB_;

    // ---- issue independent loads early ----
    const int label = __ldg(labels + b * J_ + (J_ - 1));
    // 2 neg labels per thread, coalesced int2
    const int2 ml2 = __ldg((const int2*)(neg_labels + (size_t)b * NEG_ + nbase) + tid);

    const float* cp = childrens + ((size_t)b * J_ + (J_ - 1)) * D_;
    const float4 ca = ((const float4*)cp)[lane];        // child[4*lane .. +3]
    const float4 cb = ((const float4*)cp)[lane + 32];   // child[128+4*lane ..]

    if (tid == 0) s_n = 0;
    __syncthreads();

    // ---- compaction: indices of matching negatives (2 per thread) ----
    {
        const bool h0 = (ml2.x == label);
        const bool h1 = (ml2.y == label);
        if (h0 || h1) {
            int p = atomicAdd(&s_n, (int)h0 + (int)h1);
            if (h0) s_list[p++] = (short)(tid * 2);
            if (h1) s_list[p]   = (short)(tid * 2 + 1);
        }
    }

    // ---- child norm (overlaps compaction) ----
    float cs = ca.x*ca.x + ca.y*ca.y + ca.z*ca.z + ca.w*ca.w
             + cb.x*cb.x + cb.y*cb.y + cb.z*cb.z + cb.w*cb.w;
    #pragma unroll
    for (int o = 16; o; o >>= 1) cs += __shfl_xor_sync(0xffffffffu, cs, o);
    const float invcn = 1.0f / fmaxf(sqrtf(cs), EPS_);

    // ---- chunk-0 blocks, warp 0: pos_sim for this batch ----
    if (chunk == 0 && warp == 0) {
        const float* pp = pos + ((size_t)b * J_ + (J_ - 1)) * D_;
        float4 pa = ((const float4*)pp)[lane];
        float4 pb = ((const float4*)pp)[lane + 32];
        float dot = ca.x*pa.x + ca.y*pa.y + ca.z*pa.z + ca.w*pa.w
                  + cb.x*pb.x + cb.y*pb.y + cb.z*pb.z + cb.w*pb.w;
        float ps  = pa.x*pa.x + pa.y*pa.y + pa.z*pa.z + pa.w*pa.w
                  + pb.x*pb.x + pb.y*pb.y + pb.z*pb.z + pb.w*pb.w;
        #pragma unroll
        for (int o = 16; o; o >>= 1) {
            dot += __shfl_xor_sync(0xffffffffu, dot, o);
            ps  += __shfl_xor_sync(0xffffffffu, ps,  o);
        }
        if (lane == 0)
            g_pos[b] = dot * invcn / fmaxf(sqrtf(ps), EPS_) * INV_TEMP;
    }

    __syncthreads();
    const int n = s_n;

    const float* negbase = negs + ((size_t)b * NEG_ + nbase) * D_;

    float m = -CUDART_INF_F, s = 0.0f;

    // ---- register-batched path: issue ALL owned loads first (max MLP) ----
    float4 Aa[MAXE_], Ac[MAXE_];
    #pragma unroll
    for (int k = 0; k < MAXE_; k++) {
        const int e = warp + k * WPB_;
        if (e < n) {
            const float4* p = (const float4*)(negbase + (size_t)s_list[e] * D_);
            Aa[k] = p[lane];
            Ac[k] = p[lane + 32];
        }
    }

    float dot[MAXE_], ssq[MAXE_];
    #pragma unroll
    for (int k = 0; k < MAXE_; k++) {
        const int e = warp + k * WPB_;
        if (e < n) {
            dot[k] = Aa[k].x*ca.x + Aa[k].y*ca.y + Aa[k].z*ca.z + Aa[k].w*ca.w
                   + Ac[k].x*cb.x + Ac[k].y*cb.y + Ac[k].z*cb.z + Ac[k].w*cb.w;
            ssq[k] = Aa[k].x*Aa[k].x + Aa[k].y*Aa[k].y + Aa[k].z*Aa[k].z + Aa[k].w*Aa[k].w
                   + Ac[k].x*Ac[k].x + Ac[k].y*Ac[k].y + Ac[k].z*Ac[k].z + Ac[k].w*Ac[k].w;
        } else {
            dot[k] = 0.0f; ssq[k] = 1.0f;
        }
    }

    // Interleaved butterfly reductions: 2*MAXE_ independent SHFL chains.
    #pragma unroll
    for (int o = 16; o; o >>= 1) {
        #pragma unroll
        for (int k = 0; k < MAXE_; k++) {
            dot[k] += __shfl_xor_sync(0xffffffffu, dot[k], o);
            ssq[k] += __shfl_xor_sync(0xffffffffu, ssq[k], o);
        }
    }

    // Epilogue: max then sum-exp over the owned batch.
    float sim[MAXE_];
    #pragma unroll
    for (int k = 0; k < MAXE_; k++) {
        const int e = warp + k * WPB_;
        sim[k] = (e < n) ? dot[k] * invcn / fmaxf(sqrtf(ssq[k]), EPS_) * INV_TEMP
                         : -CUDART_INF_F;
        m = fmaxf(m, sim[k]);
    }
    if (m != -CUDART_INF_F) {
        #pragma unroll
        for (int k = 0; k < MAXE_; k++)
            s += (sim[k] != -CUDART_INF_F) ? __expf(sim[k] - m) : 0.0f;
    }

    // ---- rare tail (n > 24): pipelined single-entry path ----
    for (int e = warp + MAXE_ * WPB_; e < n; e += WPB_) {
        const float4* p = (const float4*)(negbase + (size_t)s_list[e] * D_);
        float4 a = p[lane];
        float4 c = p[lane + 32];
        float d2 = a.x*ca.x + a.y*ca.y + a.z*ca.z + a.w*ca.w
                 + c.x*cb.x + c.y*cb.y + c.z*cb.z + c.w*cb.w;
        float q2 = a.x*a.x + a.y*a.y + a.z*a.z + a.w*a.w
                 + c.x*c.x + c.y*c.y + c.z*c.z + c.w*c.w;
        #pragma unroll
        for (int o = 16; o; o >>= 1) {
            d2 += __shfl_xor_sync(0xffffffffu, d2, o);
            q2 += __shfl_xor_sync(0xffffffffu, q2, o);
        }
        float sm = d2 * invcn / fmaxf(sqrtf(q2), EPS_) * INV_TEMP;
        float M2 = fmaxf(m, sm);
        s = s * __expf(m - M2) + __expf(sm - M2);
        m = M2;
    }

    if (lane == 0) { s_m[warp] = m; s_s[warp] = s; }
    __syncthreads();

    // ---- thread 0: combine warp partials, publish block partial ----
    if (tid == 0) {
        float mm = s_m[0], sv = s_s[0];
        #pragma unroll
        for (int w = 1; w < WPB_; w++) lse_comb(mm, sv, s_m[w], s_s[w]);
        g_part[bx] = make_float2(mm, sv);
    }

    // ---- arrival: last block finalizes ----
    __threadfence();
    if (tid == 0) {
        unsigned int old = atomicAdd(&g_count, 1u);
        s_last = (old == NBLOCKS_ - 1) ? 1 : 0;
    }
    __syncthreads();
    if (!s_last) return;

    __threadfence();  // make all blocks' partials visible

    __shared__ float s_loss[B_];
    if (tid < B_) {
        const int batch = tid;
        float m2 = -CUDART_INF_F, s2 = 0.0f;
        #pragma unroll
        for (int k = 0; k < SPLIT_; k++) {
            float2 pr = g_part[batch * SPLIT_ + k];
            lse_comb(m2, s2, pr.x, pr.y);
        }
        const float psim = g_pos[batch];
        lse_comb(m2, s2, psim, 1.0f);
        s_loss[batch] = m2 + logf(s2) - psim;
    }
    __syncthreads();

    if (tid < 32) {
        float v = s_loss[tid] + s_loss[tid + 32];
        #pragma unroll
        for (int o = 16; o; o >>= 1) v += __shfl_xor_sync(0xffffffffu, v, o);
        if (tid == 0) {
            out[0] = v / (2.0f * (float)B_);
            g_count = 0;   // reset for next (graph-replayed) launch
        }
    }
}

extern "C" void kernel_launch(void* const* d_in, const int* in_sizes, int n_in,
                              void* d_out, int out_size) {
    const float* childrens  = (const float*)d_in[0]; // (B, J, D)
    const float* child_pos  = (const float*)d_in[1]; // (B, J, D)
    const float* child_negs = (const float*)d_in[2]; // (B, K, M, D)
    const int*   gt_labels  = (const int*)d_in[3];   // (B, J)
    const int*   gt_negs    = (const int*)d_in[4];   // (B, K, M)
    float* out = (float*)d_out;

    ntxent_kernel<<<NBLOCKS_, THREADS_>>>(childrens, child_pos, child_negs,
                                          gt_labels, gt_negs, out);
}